// round 2
// baseline (speedup 1.0000x reference)
#include <cuda_runtime.h>
#include <math.h>

// Problem constants (B=1)
#define NH    16
#define NSEQ  8192
#define EDIM  64
#define CHUNKN 512
#define NCH   16
#define RT    64      // query rows per block
#define KTL   128     // key cols per smem tile
#define SCALE 0.125f  // 1/sqrt(64)
#define WCOLS 15872   // 512 + 15*1024

// smem leading dims (floats); chosen to keep float4 (16B) alignment of row bases
#define QT_LD 68
#define KV_LD 132
#define S_LD  516

#define SM_QT 0
#define SM_KV (64 * QT_LD)
#define SM_S  (SM_KV + 64 * KV_LD)
#define SMEM_FLOATS (SM_S + RT * S_LD)   // 45824 floats = 183296 B

__global__ __launch_bounds__(256, 1)
void chunked_attn_kernel(const float* __restrict__ query,
                         const float* __restrict__ key,
                         const float* __restrict__ value,
                         float* __restrict__ out,
                         float* __restrict__ wts)
{
    extern __shared__ float sm[];
    float* Qt = sm + SM_QT;   // Qt[e][i]   (e-major, i = local row)
    float* KV = sm + SM_KV;   // KV[e][jj]  (e-major; K tile, later V tile)
    float* S  = sm + SM_S;    // S[i][j]    (scores -> exp -> normalized A)

    const int tid  = threadIdx.x;
    const int tx   = tid & 15;
    const int ty   = tid >> 4;
    const int lane = tid & 31;
    const int wid  = tid >> 5;

    const int rt = blockIdx.x;          // row tile 0..7
    const int n  = blockIdx.y;          // chunk 0..15
    const int h  = blockIdx.z;          // head
    const int r0 = rt * RT;
    const int m  = (n == 0) ? 0 : n - 1;  // effective key/value chunk

    const float* qbase = query + ((size_t)h * NSEQ + (size_t)n * CHUNKN + r0) * EDIM;
    const float* kbase = key   + ((size_t)h * NSEQ + (size_t)m * CHUNKN) * EDIM;
    const float* vbase = value + ((size_t)h * NSEQ + (size_t)m * CHUNKN) * EDIM;

    // ---- load Q tile transposed: Qt[e][i] ----
    for (int idx = tid; idx < RT * EDIM; idx += 256) {
        int i = idx >> 6, e = idx & 63;
        Qt[e * QT_LD + i] = qbase[(size_t)i * EDIM + e];
    }

    const int ktmax = (r0 + RT - 1) >> 7;   // highest key tile with any unmasked col
    const int jend  = (ktmax + 1) * KTL;

    // ==================== GEMM1: S = scale * Q K^T (only live tiles) ====================
    for (int kt = 0; kt <= ktmax; kt++) {
        const int j0 = kt * KTL;
        __syncthreads();   // protect KV (and order Qt stores on first iter)
        for (int idx = tid; idx < KTL * EDIM; idx += 256) {
            int jj = idx >> 6, e = idx & 63;
            KV[e * KV_LD + jj] = kbase[(size_t)(j0 + jj) * EDIM + e];
        }
        __syncthreads();

        float acc[4][8];
        #pragma unroll
        for (int a = 0; a < 4; a++)
            #pragma unroll
            for (int b = 0; b < 8; b++) acc[a][b] = 0.f;

        const float* qb = Qt + ty * 4;
        const float* kb = KV + tx * 8;
        #pragma unroll 8
        for (int e = 0; e < EDIM; e++) {
            float4 qv = *(const float4*)(qb + e * QT_LD);
            float4 k0 = *(const float4*)(kb + e * KV_LD);
            float4 k1 = *(const float4*)(kb + e * KV_LD + 4);
            float qs[4] = {qv.x, qv.y, qv.z, qv.w};
            float ks[8] = {k0.x, k0.y, k0.z, k0.w, k1.x, k1.y, k1.z, k1.w};
            #pragma unroll
            for (int a = 0; a < 4; a++)
                #pragma unroll
                for (int b = 0; b < 8; b++)
                    acc[a][b] = fmaf(qs[a], ks[b], acc[a][b]);
        }

        // masked entries are never read later (softmax loops are bounded), so store raw
        float* srow = S + (ty * 4) * S_LD + j0 + tx * 8;
        #pragma unroll
        for (int a = 0; a < 4; a++)
            #pragma unroll
            for (int b = 0; b < 8; b++)
                srow[a * S_LD + b] = acc[a][b] * SCALE;
    }

    __syncthreads();

    // ==================== softmax + weights write (warp per row, 8 rows/warp) ====================
    const int wcolbase = (n == 0) ? 0 : 512 + (n - 1) * 1024;
    for (int i = wid * 8; i < wid * 8 + 8; i++) {
        const int rglob = r0 + i;        // row index within chunk, 0..511
        float* srow = S + i * S_LD;

        float mx = -INFINITY;
        for (int j = lane; j <= rglob; j += 32) mx = fmaxf(mx, srow[j]);
        #pragma unroll
        for (int off = 16; off; off >>= 1) mx = fmaxf(mx, __shfl_xor_sync(0xffffffffu, mx, off));

        float sum = 0.f;
        for (int j = lane; j <= rglob; j += 32) {
            float ex = __expf(srow[j] - mx);
            srow[j] = ex;
            sum += ex;
        }
        #pragma unroll
        for (int off = 16; off; off >>= 1) sum += __shfl_xor_sync(0xffffffffu, sum, off);
        float inv = 1.f / sum;

        float* wrow = wts + ((size_t)h * CHUNKN + rglob) * WCOLS + wcolbase;
        for (int j = lane; j < jend; j += 32) {
            float a = (j <= rglob) ? srow[j] * inv : 0.f;
            srow[j] = a;            // zero the masked region before GEMM2 reads it
            wrow[j] = a;
        }
        for (int j = jend + lane; j < CHUNKN; j += 32) wrow[j] = 0.f;
        if (n > 0)  // second half of the 2c window is fully masked -> exact zeros
            for (int j = CHUNKN + lane; j < 2 * CHUNKN; j += 32) wrow[j] = 0.f;
    }

    // ==================== GEMM2: O = A V (only live tiles) ====================
    float acc2[4][4];
    #pragma unroll
    for (int a = 0; a < 4; a++)
        #pragma unroll
        for (int b = 0; b < 4; b++) acc2[a][b] = 0.f;

    for (int kt = 0; kt <= ktmax; kt++) {
        const int j0 = kt * KTL;
        __syncthreads();   // softmax done (first iter) / KV free (later iters)
        for (int idx = tid; idx < KTL * EDIM; idx += 256) {
            int jj = idx >> 6, e = idx & 63;
            KV[e * KV_LD + jj] = vbase[(size_t)(j0 + jj) * EDIM + e];   // Vt[e][jj]
        }
        __syncthreads();

        const float* sb = S + (ty * 4) * S_LD + j0;
        const float* vb = KV + (tx * 4) * KV_LD;
        #pragma unroll 8
        for (int j = 0; j < KTL; j += 4) {
            float4 av[4], vv[4];
            #pragma unroll
            for (int a = 0; a < 4; a++) av[a] = *(const float4*)(sb + a * S_LD + j);
            #pragma unroll
            for (int b = 0; b < 4; b++) vv[b] = *(const float4*)(vb + b * KV_LD + j);
            #pragma unroll
            for (int a = 0; a < 4; a++)
                #pragma unroll
                for (int b = 0; b < 4; b++) {
                    acc2[a][b] = fmaf(av[a].x, vv[b].x, acc2[a][b]);
                    acc2[a][b] = fmaf(av[a].y, vv[b].y, acc2[a][b]);
                    acc2[a][b] = fmaf(av[a].z, vv[b].z, acc2[a][b]);
                    acc2[a][b] = fmaf(av[a].w, vv[b].w, acc2[a][b]);
                }
        }
    }

    float* optr = out + ((size_t)h * NSEQ + (size_t)n * CHUNKN + r0) * EDIM;
    #pragma unroll
    for (int a = 0; a < 4; a++) {
        float4 v4 = make_float4(acc2[a][0], acc2[a][1], acc2[a][2], acc2[a][3]);
        *(float4*)(optr + (size_t)(ty * 4 + a) * EDIM + tx * 4) = v4;
    }
}

extern "C" void kernel_launch(void* const* d_in, const int* in_sizes, int n_in,
                              void* d_out, int out_size)
{
    const float* q = (const float*)d_in[0];
    const float* k = (const float*)d_in[1];
    const float* v = (const float*)d_in[2];
    float* out = (float*)d_out;
    float* wts = out + (size_t)NH * NSEQ * EDIM;   // weights follow output in d_out

    size_t smem = (size_t)SMEM_FLOATS * sizeof(float);   // 183296 B
    cudaFuncSetAttribute(chunked_attn_kernel,
                         cudaFuncAttributeMaxDynamicSharedMemorySize, (int)smem);

    dim3 grid(CHUNKN / RT, NCH, NH);   // 8 x 16 x 16 = 2048 blocks
    chunked_attn_kernel<<<grid, 256, smem>>>(q, k, v, out, wts);
}